// round 12
// baseline (speedup 1.0000x reference)
#include <cuda_runtime.h>
#include <cstdint>

#define BATCH 4096

// ---------------- Device scratch ----------------
__device__ unsigned g_w1p[20];                          // 25 sign bits per filter
__device__ __align__(16) signed char g_w2i8[5*56*144];  // B: [ky][f(56)][j(144)] int8 +-1, pad 0
__device__ __align__(16) unsigned g_w3p[1024*80];       // per out-neuron: 2450 bits (order pix*50+c), pad 80
__device__ unsigned g_w4p[10*32];                       // per out-neuron: 1024 sign bits
__device__ unsigned g_xrow[BATCH*64];                   // per image: mask rows / sign rows
__device__ __align__(16) unsigned char g_a1[BATCH*6480];// conv1 out: padded 18x18x20 bytes {0,1}, channel-last
__device__ __align__(16) unsigned g_packed2[BATCH*80];  // fc3 input bits (order pix*50+c), padded
__device__ unsigned g_packed3[BATCH*32];                // fc4 input bits (1024)

// ---------------- w3 packing: block per out-neuron, coalesced + smem transpose ----------------
__global__ void __launch_bounds__(128) pack_w3_kernel(const float* __restrict__ w3) {
    __shared__ unsigned char sb[2450];
    int o = blockIdx.x, tid = threadIdx.x;
    const float* row = w3 + o * 2450;
    for (int j = tid; j < 2450; j += 128) sb[j] = (row[j] > 0.0f);
    __syncthreads();
    if (tid < 80) {
        unsigned m = 0; int base = tid * 32;
        for (int k = 0; k < 32; k++) {
            int jp = base + k;
            if (jp < 2450) {
                int pix = jp / 50, c = jp % 50;   // orig flat index = c*49 + pix
                m |= (unsigned)sb[c*49 + pix] << k;
            }
        }
        g_w3p[o*80 + tid] = m;
    }
}

// ---------------- small weights: w1 | w2i8 | w4 ----------------
// ranges: [0,20) w1 | [20,40340) w2i8 | [40340,40660) w4
__global__ void pack_wsm_kernel(const float* __restrict__ w1, const float* __restrict__ w2,
                                const float* __restrict__ w4) {
    int id = blockIdx.x * blockDim.x + threadIdx.x;
    if (id < 20) {
        unsigned m = 0;
        #pragma unroll
        for (int t = 0; t < 25; t++) m |= (unsigned)(w1[id*25 + t] > 0.0f) << t;
        g_w1p[id] = m;
    } else if (id < 40340) {
        int idx = id - 20;
        int ky = idx / 8064, r2 = idx % 8064;
        int f = r2 / 144, j = r2 % 144;
        signed char v = 0;
        if (j < 100 && f < 50) {
            int c = j % 20, kx = j / 20;
            v = (w2[f*500 + c*25 + ky*5 + kx] > 0.0f) ? 1 : -1;
        }
        g_w2i8[idx] = v;
    } else if (id < 40660) {
        int idx = id - 40340; int o = idx / 32, w = idx % 32;
        unsigned m = 0;
        #pragma unroll
        for (int k = 0; k < 32; k++) m |= (unsigned)(w4[o*1024 + w*32 + k] > 0.0f) << k;
        g_w4p[idx] = m;
    }
}

// ---------------- pack x into per-row mask/sign bit words ----------------
__global__ void pack_xrow_kernel(const float* __restrict__ x) {
    int id = blockIdx.x * 128 + threadIdx.x;          // 1024*128 = 4096*32
    int b = id >> 5, r = id & 31;
    unsigned m = 0, p = 0;
    if (r >= 2 && r < 30) {
        const float* row = x + b*784 + (r-2)*28;
        #pragma unroll
        for (int xx = 0; xx < 28; xx++) {
            float v = row[xx];
            m |= (unsigned)(v != 0.0f) << (xx + 2);
            p |= (unsigned)(v > 0.0f)  << (xx + 2);
        }
    }
    g_xrow[b*64 + r]      = m;
    g_xrow[b*64 + 32 + r] = p;
}

// ---------------- conv1 + relu + maxpool2 + sign -> channel-last bytes (padded 18x18x20) ----------------
__global__ void __launch_bounds__(128) conv1_kernel(const float* __restrict__ b1) {
    __shared__ unsigned w1s[20];
    __shared__ float b1s[20];
    int tid = threadIdx.x;
    if (tid < 20) { w1s[tid] = g_w1p[tid]; b1s[tid] = b1[tid]; }
    __syncthreads();

    int id = blockIdx.x * 128 + tid;                 // 6272*128 = 4096*196
    int b = id / 196, pix = id % 196;
    int py = pix / 14, px = pix % 14;
    unsigned char* a1b = g_a1 + b * 6480;

    // zero the 128 border pixels of the padded 18x18 image
    if (pix < 128) {
        int y, xx;
        if (pix < 72) { int ry = pix / 18; y = (ry < 2) ? ry : ry + 14; xx = pix % 18; }
        else { int j = pix - 72; int cx = j % 4; xx = (cx < 2) ? cx : cx + 14; y = 2 + j / 4; }
        unsigned* d = (unsigned*)(a1b + (y*18 + xx)*20);
        #pragma unroll
        for (int q = 0; q < 5; q++) d[q] = 0u;
    }

    const unsigned* xr = g_xrow + b*64;
    unsigned mr[6], pr[6];
    #pragma unroll
    for (int i = 0; i < 6; i++) { mr[i] = xr[2*py + i]; pr[i] = xr[32 + 2*py + i]; }

    unsigned M[4], P[4]; int pm[4];
    #pragma unroll
    for (int dy = 0; dy < 2; dy++)
    #pragma unroll
    for (int dx = 0; dx < 2; dx++) {
        int sh = 2*px + dx;
        unsigned m = 0, p = 0;
        #pragma unroll
        for (int ky = 0; ky < 5; ky++) {
            m |= ((mr[dy + ky] >> sh) & 31u) << (5*ky);
            p |= ((pr[dy + ky] >> sh) & 31u) << (5*ky);
        }
        int w = dy*2 + dx;
        M[w] = m; P[w] = p; pm[w] = __popc(m);
    }

    unsigned word = 0;
    #pragma unroll
    for (int c = 0; c < 20; c++) {
        unsigned wp = w1s[c];
        int d0 = 2*__popc(M[0] & ~(P[0] ^ wp)) - pm[0];
        int d1 = 2*__popc(M[1] & ~(P[1] ^ wp)) - pm[1];
        int d2 = 2*__popc(M[2] & ~(P[2] ^ wp)) - pm[2];
        int d3 = 2*__popc(M[3] & ~(P[3] ^ wp)) - pm[3];
        int mx = max(max(d0, d1), max(d2, d3));
        if ((float)mx + b1s[c] > 0.0f) word |= 1u << c;
    }

    // expand 20 bits -> 20 bytes {0,1} at padded (py+2, px+2)
    unsigned* dst = (unsigned*)(a1b + ((py+2)*18 + (px+2))*20);
    #pragma unroll
    for (int q = 0; q < 5; q++) {
        unsigned u = ((word >> (4*q)) & 1u)
                   | (((word >> (4*q+1)) & 1u) << 8)
                   | (((word >> (4*q+2)) & 1u) << 16)
                   | (((word >> (4*q+3)) & 1u) << 24);
        dst[q] = u;
    }
}

// ---------------- conv2 via int8 mma + ldmatrix; 2 images per CTA ----------------
#define NT 7
#define OFF_B    0          // 40320 (5*56*144)
#define OFF_IMG  40320      // 12960 (2*6480)
#define OFF_THR  53280      // 224
#define OFF_PACK 53504      // 320
#define OFF_A    53824      // 29952 (208*144)
#define OFF_V    83776      // 23296 (208*112)
#define SMEM_SZ  107072

__device__ __forceinline__ void mma_s8(int* d, unsigned a0, unsigned a1, unsigned a2, unsigned a3,
                                       unsigned b0, unsigned b1) {
    asm volatile("mma.sync.aligned.m16n8k32.row.col.s32.s8.s8.s32 "
                 "{%0,%1,%2,%3},{%4,%5,%6,%7},{%8,%9},{%0,%1,%2,%3};"
                 : "+r"(d[0]), "+r"(d[1]), "+r"(d[2]), "+r"(d[3])
                 : "r"(a0), "r"(a1), "r"(a2), "r"(a3), "r"(b0), "r"(b1));
}
__device__ __forceinline__ void ldsm4(unsigned& r0, unsigned& r1, unsigned& r2, unsigned& r3, unsigned addr) {
    asm volatile("ldmatrix.sync.aligned.m8n8.x4.shared.b16 {%0,%1,%2,%3},[%4];"
                 : "=r"(r0), "=r"(r1), "=r"(r2), "=r"(r3) : "r"(addr));
}
__device__ __forceinline__ void ldsm2(unsigned& r0, unsigned& r1, unsigned addr) {
    asm volatile("ldmatrix.sync.aligned.m8n8.x2.shared.b16 {%0,%1},[%2];"
                 : "=r"(r0), "=r"(r1) : "r"(addr));
}

__global__ void __launch_bounds__(256) conv2_mma2_kernel(const float* __restrict__ b2) {
    extern __shared__ __align__(16) unsigned char smem[];
    unsigned sbase = (unsigned)__cvta_generic_to_shared(smem);
    int tid = threadIdx.x, wid = tid >> 5, lane = tid & 31;
    int gr = lane >> 2, tig = lane & 3;
    int j8 = lane >> 3, r8 = lane & 7;

    // stage B weights (2520 uint4), thresholds, both images (810 uint4)
    {
        const uint4* s = (const uint4*)g_w2i8;
        uint4* d = (uint4*)(smem + OFF_B);
        for (int t = tid; t < 2520; t += 256) d[t] = s[t];
    }
    if (tid < 50) ((int*)(smem + OFF_THR))[tid] = (int)floorf(-b2[tid]) + 1;
    {
        const uint4* s = (const uint4*)(g_a1 + (size_t)blockIdx.x * 12960);
        uint4* d = (uint4*)(smem + OFF_IMG);
        for (int t = tid; t < 810; t += 256) d[t] = s[t];
    }
    __syncthreads();

    bool has1 = (wid < 5);
    unsigned aRowOff = (unsigned)(r8 + ((j8 & 1) << 3));   // row within m16 tile for this lane
    unsigned aByte = (unsigned)((j8 >> 1) << 4);           // 0 or 16 (k halves)
    unsigned jb = (unsigned)((lane >> 3) & 1), rbl = (unsigned)(lane & 7);

    #pragma unroll 1
    for (int img = 0; img < 2; img++) {
        if (tid < 80) ((unsigned*)(smem + OFF_PACK))[tid] = 0u;

        int acc[2][NT][4];
        #pragma unroll
        for (int m = 0; m < 2; m++)
            #pragma unroll
            for (int n = 0; n < NT; n++)
                #pragma unroll
                for (int k = 0; k < 4; k++) acc[m][n][k] = 0;

        #pragma unroll 1
        for (int ky = 0; ky < 5; ky++) {
            // build A [196 x 128B used] (row stride 144)
            if (tid < 196) {
                int cy = tid / 14, cx = tid % 14;
                const unsigned* src = (const unsigned*)(smem + OFF_IMG + img*6480 + ((cy + ky)*18 + cx)*20);
                unsigned v[32];
                #pragma unroll
                for (int q = 0; q < 25; q++) v[q] = src[q];
                #pragma unroll
                for (int q = 25; q < 32; q++) v[q] = 0u;
                uint4* dst = (uint4*)(smem + OFF_A + tid*144);
                #pragma unroll
                for (int q = 0; q < 8; q++) dst[q] = make_uint4(v[q*4], v[q*4+1], v[q*4+2], v[q*4+3]);
            }
            __syncthreads();

            #pragma unroll
            for (int ks = 0; ks < 4; ks++) {
                unsigned a00,a01,a02,a03, a10=0,a11=0,a12=0,a13=0;
                ldsm4(a00,a01,a02,a03, sbase + OFF_A + (wid*16 + aRowOff)*144 + ks*32 + aByte);
                if (has1)
                    ldsm4(a10,a11,a12,a13, sbase + OFF_A + ((8 + wid)*16 + aRowOff)*144 + ks*32 + aByte);
                #pragma unroll
                for (int nt = 0; nt < NT; nt++) {
                    unsigned b0, b1;
                    ldsm2(b0, b1, sbase + OFF_B + ky*8064 + (nt*8 + rbl)*144 + ks*32 + jb*16);
                    mma_s8(acc[0][nt], a00,a01,a02,a03, b0,b1);
                    if (has1) mma_s8(acc[1][nt], a10,a11,a12,a13, b0,b1);
                }
            }
            __syncthreads();
        }

        // dump conv values to V (int16 [208][56], row stride 112B)
        {
            unsigned* V = (unsigned*)(smem + OFF_V);
            #pragma unroll
            for (int mt = 0; mt < 2; mt++) {
                if (mt == 1 && !has1) break;
                int mb = (mt == 0 ? wid : 8 + wid) * 16;
                #pragma unroll
                for (int nt = 0; nt < NT; nt++) {
                    int n = nt*8 + 2*tig;
                    int m = mb + gr;
                    V[m*28 + (n >> 1)]     = ((unsigned)acc[mt][nt][0] & 0xffffu) | ((unsigned)acc[mt][nt][1] << 16);
                    V[(m+8)*28 + (n >> 1)] = ((unsigned)acc[mt][nt][2] & 0xffffu) | ((unsigned)acc[mt][nt][3] << 16);
                }
            }
        }
        __syncthreads();

        // pool + threshold + pack bits (bit index pp*50 + f)
        {
            const short* V = (const short*)(smem + OFF_V);
            const int* thr = (const int*)(smem + OFF_THR);
            unsigned* pack = (unsigned*)(smem + OFF_PACK);
            for (int it = tid; it < 2450; it += 256) {
                int pp = it / 50, f = it % 50;
                int y = pp / 7, x = pp % 7;
                int m00 = (2*y)*14 + 2*x;
                int v0 = V[m00*56 + f];
                int v1 = V[(m00+1)*56 + f];
                int v2 = V[(m00+14)*56 + f];
                int v3 = V[(m00+15)*56 + f];
                int mx = max(max(v0, v1), max(v2, v3));
                if (mx >= thr[f]) {
                    int bi = pp*50 + f;
                    atomicOr(&pack[bi >> 5], 1u << (bi & 31));
                }
            }
        }
        __syncthreads();
        if (tid < 20)
            ((uint4*)(g_packed2 + (size_t)(2*blockIdx.x + img)*80))[tid] = ((const uint4*)(smem + OFF_PACK))[tid];
        __syncthreads();
    }
}

// ---------------- fc3: register-tiled 4 outputs x 8 batches per thread ----------------
__global__ void __launch_bounds__(128) fc3_kernel(const float* __restrict__ b3) {
    __shared__ __align__(16) unsigned sa[8*80];
    __shared__ int sna[8];
    int tid = threadIdx.x;
    int b0 = blockIdx.y * 8;
    for (int t = tid; t < 160; t += 128)
        ((uint4*)sa)[t] = ((const uint4*)(g_packed2 + b0*80))[t];
    __syncthreads();
    if (tid < 8) {
        int s = 0;
        #pragma unroll 8
        for (int i = 0; i < 80; i++) s += __popc(sa[tid*80 + i]);
        sna[tid] = s;
    }
    __syncthreads();

    int obase = blockIdx.x * 512 + tid;
    const uint4* wr0 = (const uint4*)(g_w3p + (obase      )*80);
    const uint4* wr1 = (const uint4*)(g_w3p + (obase + 128)*80);
    const uint4* wr2 = (const uint4*)(g_w3p + (obase + 256)*80);
    const uint4* wr3 = (const uint4*)(g_w3p + (obase + 384)*80);

    int cnt[4][8];
    #pragma unroll
    for (int j = 0; j < 4; j++)
        #pragma unroll
        for (int bb = 0; bb < 8; bb++) cnt[j][bb] = 0;

    #pragma unroll 2
    for (int i = 0; i < 20; i++) {
        uint4 w[4] = {wr0[i], wr1[i], wr2[i], wr3[i]};
        #pragma unroll
        for (int bb = 0; bb < 8; bb++) {
            uint4 a = *(const uint4*)&sa[bb*80 + i*4];
            #pragma unroll
            for (int j = 0; j < 4; j++) {
                cnt[j][bb] += __popc(a.x & w[j].x) + __popc(a.y & w[j].y)
                            + __popc(a.z & w[j].z) + __popc(a.w & w[j].w);
            }
        }
    }

    #pragma unroll
    for (int j = 0; j < 4; j++) {
        int o = obase + 128*j;
        float bias = b3[o];
        int widx = o >> 5;
        #pragma unroll
        for (int bb = 0; bb < 8; bb++) {
            float val = (float)(2*cnt[j][bb] - sna[bb]) + bias;
            unsigned word = __ballot_sync(0xffffffffu, val > 0.0f);
            if ((tid & 31) == 0) g_packed3[(b0 + bb)*32 + widx] = word;
        }
    }
}

// ---------------- fc4 ----------------
__global__ void __launch_bounds__(128) fc4_kernel(const float* __restrict__ b4, float* __restrict__ out) {
    __shared__ unsigned w4s[10*32];
    __shared__ float b4s[10];
    int tid = threadIdx.x;
    for (int t = tid; t < 320; t += 128) w4s[t] = g_w4p[t];
    if (tid < 10) b4s[tid] = b4[tid];
    __syncthreads();

    int b = blockIdx.x * 128 + tid;
    unsigned a[32]; int na = 0;
    #pragma unroll
    for (int i = 0; i < 32; i++) { a[i] = g_packed3[b*32 + i]; na += __popc(a[i]); }
    #pragma unroll
    for (int k = 0; k < 10; k++) {
        int cnt = 0;
        #pragma unroll
        for (int i = 0; i < 32; i++) cnt += __popc(a[i] & w4s[k*32 + i]);
        out[b*10 + k] = (float)(2*cnt - na) + b4s[k];
    }
}

// ---------------- launch ----------------
extern "C" void kernel_launch(void* const* d_in, const int* in_sizes, int n_in,
                              void* d_out, int out_size) {
    const float* x  = (const float*)d_in[0];
    const float* w1 = (const float*)d_in[1];
    const float* b1 = (const float*)d_in[2];
    const float* w2 = (const float*)d_in[3];
    const float* b2 = (const float*)d_in[4];
    const float* w3 = (const float*)d_in[5];
    const float* b3 = (const float*)d_in[6];
    const float* w4 = (const float*)d_in[7];
    const float* b4 = (const float*)d_in[8];
    float* out = (float*)d_out;

    cudaFuncSetAttribute(conv2_mma2_kernel, cudaFuncAttributeMaxDynamicSharedMemorySize, SMEM_SZ);

    pack_w3_kernel<<<1024, 128>>>(w3);               // block per out-neuron
    pack_wsm_kernel<<<318, 128>>>(w1, w2, w4);       // 40660 items
    pack_xrow_kernel<<<1024, 128>>>(x);              // 4096*32 rows
    conv1_kernel<<<6272, 128>>>(b1);                 // 4096*196
    conv2_mma2_kernel<<<2048, 256, SMEM_SZ>>>(b2);   // 2 images per CTA
    fc3_kernel<<<dim3(2, 512), 128>>>(b3);           // 1024 outs x (4096/8)
    fc4_kernel<<<32, 128>>>(b4, out);                // 4096
}

// round 13
// speedup vs baseline: 1.0069x; 1.0069x over previous
#include <cuda_runtime.h>
#include <cstdint>

#define BATCH 4096

// ---------------- Device scratch ----------------
__device__ unsigned g_w1p[20];                          // 25 sign bits per filter
__device__ __align__(16) signed char g_w2i8[5*56*144];  // B: [ky][f(56)][j(144)] int8 +-1, pad 0
__device__ __align__(16) unsigned g_w3p[1024*80];       // per out-neuron: 2450 bits (order pix*50+c), pad 80
__device__ unsigned g_w4p[10*32];                       // per out-neuron: 1024 sign bits
__device__ unsigned g_xrow[BATCH*64];                   // per image: mask rows / sign rows
__device__ __align__(16) unsigned char g_a1[BATCH*6480];// conv1 out: padded 18x18x20 bytes {0,1}, channel-last
__device__ __align__(16) unsigned g_packed2[BATCH*80];  // fc3 input bits (order pix*50+c), padded
__device__ unsigned g_packed3[BATCH*32];                // fc4 input bits (1024)

// ---------------- w3 packing: block per out-neuron, coalesced + smem transpose ----------------
__global__ void __launch_bounds__(128) pack_w3_kernel(const float* __restrict__ w3) {
    __shared__ unsigned char sb[2450];
    int o = blockIdx.x, tid = threadIdx.x;
    const float* row = w3 + o * 2450;
    for (int j = tid; j < 2450; j += 128) sb[j] = (row[j] > 0.0f);
    __syncthreads();
    if (tid < 80) {
        unsigned m = 0; int base = tid * 32;
        for (int k = 0; k < 32; k++) {
            int jp = base + k;
            if (jp < 2450) {
                int pix = jp / 50, c = jp % 50;   // orig flat index = c*49 + pix
                m |= (unsigned)sb[c*49 + pix] << k;
            }
        }
        g_w3p[o*80 + tid] = m;
    }
}

// ---------------- small weights: w1 | w2i8 | w4 ----------------
// ranges: [0,20) w1 | [20,40340) w2i8 | [40340,40660) w4
__global__ void pack_wsm_kernel(const float* __restrict__ w1, const float* __restrict__ w2,
                                const float* __restrict__ w4) {
    int id = blockIdx.x * blockDim.x + threadIdx.x;
    if (id < 20) {
        unsigned m = 0;
        #pragma unroll
        for (int t = 0; t < 25; t++) m |= (unsigned)(w1[id*25 + t] > 0.0f) << t;
        g_w1p[id] = m;
    } else if (id < 40340) {
        int idx = id - 20;
        int ky = idx / 8064, r2 = idx % 8064;
        int f = r2 / 144, j = r2 % 144;
        signed char v = 0;
        if (j < 100 && f < 50) {
            int c = j % 20, kx = j / 20;
            v = (w2[f*500 + c*25 + ky*5 + kx] > 0.0f) ? 1 : -1;
        }
        g_w2i8[idx] = v;
    } else if (id < 40660) {
        int idx = id - 40340; int o = idx / 32, w = idx % 32;
        unsigned m = 0;
        #pragma unroll
        for (int k = 0; k < 32; k++) m |= (unsigned)(w4[o*1024 + w*32 + k] > 0.0f) << k;
        g_w4p[idx] = m;
    }
}

// ---------------- pack x into per-row mask/sign bit words ----------------
__global__ void pack_xrow_kernel(const float* __restrict__ x) {
    int id = blockIdx.x * 128 + threadIdx.x;          // 1024*128 = 4096*32
    int b = id >> 5, r = id & 31;
    unsigned m = 0, p = 0;
    if (r >= 2 && r < 30) {
        const float* row = x + b*784 + (r-2)*28;
        #pragma unroll
        for (int xx = 0; xx < 28; xx++) {
            float v = row[xx];
            m |= (unsigned)(v != 0.0f) << (xx + 2);
            p |= (unsigned)(v > 0.0f)  << (xx + 2);
        }
    }
    g_xrow[b*64 + r]      = m;
    g_xrow[b*64 + 32 + r] = p;
}

// ---------------- conv1 + relu + maxpool2 + sign -> channel-last bytes (padded 18x18x20) ----------------
__global__ void __launch_bounds__(128) conv1_kernel(const float* __restrict__ b1) {
    __shared__ unsigned w1s[20];
    __shared__ float b1s[20];
    int tid = threadIdx.x;
    if (tid < 20) { w1s[tid] = g_w1p[tid]; b1s[tid] = b1[tid]; }
    __syncthreads();

    int id = blockIdx.x * 128 + tid;                 // 6272*128 = 4096*196
    int b = id / 196, pix = id % 196;
    int py = pix / 14, px = pix % 14;
    unsigned char* a1b = g_a1 + b * 6480;

    if (pix < 128) {
        int y, xx;
        if (pix < 72) { int ry = pix / 18; y = (ry < 2) ? ry : ry + 14; xx = pix % 18; }
        else { int j = pix - 72; int cx = j % 4; xx = (cx < 2) ? cx : cx + 14; y = 2 + j / 4; }
        unsigned* d = (unsigned*)(a1b + (y*18 + xx)*20);
        #pragma unroll
        for (int q = 0; q < 5; q++) d[q] = 0u;
    }

    const unsigned* xr = g_xrow + b*64;
    unsigned mr[6], pr[6];
    #pragma unroll
    for (int i = 0; i < 6; i++) { mr[i] = xr[2*py + i]; pr[i] = xr[32 + 2*py + i]; }

    unsigned M[4], P[4]; int pm[4];
    #pragma unroll
    for (int dy = 0; dy < 2; dy++)
    #pragma unroll
    for (int dx = 0; dx < 2; dx++) {
        int sh = 2*px + dx;
        unsigned m = 0, p = 0;
        #pragma unroll
        for (int ky = 0; ky < 5; ky++) {
            m |= ((mr[dy + ky] >> sh) & 31u) << (5*ky);
            p |= ((pr[dy + ky] >> sh) & 31u) << (5*ky);
        }
        int w = dy*2 + dx;
        M[w] = m; P[w] = p; pm[w] = __popc(m);
    }

    unsigned word = 0;
    #pragma unroll
    for (int c = 0; c < 20; c++) {
        unsigned wp = w1s[c];
        int d0 = 2*__popc(M[0] & ~(P[0] ^ wp)) - pm[0];
        int d1 = 2*__popc(M[1] & ~(P[1] ^ wp)) - pm[1];
        int d2 = 2*__popc(M[2] & ~(P[2] ^ wp)) - pm[2];
        int d3 = 2*__popc(M[3] & ~(P[3] ^ wp)) - pm[3];
        int mx = max(max(d0, d1), max(d2, d3));
        if ((float)mx + b1s[c] > 0.0f) word |= 1u << c;
    }

    unsigned* dst = (unsigned*)(a1b + ((py+2)*18 + (px+2))*20);
    #pragma unroll
    for (int q = 0; q < 5; q++) {
        unsigned u = ((word >> (4*q)) & 1u)
                   | (((word >> (4*q+1)) & 1u) << 8)
                   | (((word >> (4*q+2)) & 1u) << 16)
                   | (((word >> (4*q+3)) & 1u) << 24);
        dst[q] = u;
    }
}

// ---------------- conv2 via int8 mma + ldmatrix; 2 images per CTA; A/V aliased ----------------
#define NT 7
#define OFF_B    0          // 40320 (5*56*144)
#define OFF_IMG  40320      // 12960 (2*6480)
#define OFF_THR  53280      // 224
#define OFF_PACK 53504      // 320
#define OFF_AV   53824      // union: A 29952 (208*144) / V 23296 (208*112)
#define SMEM_SZ  83776

__device__ __forceinline__ void mma_s8(int* d, unsigned a0, unsigned a1, unsigned a2, unsigned a3,
                                       unsigned b0, unsigned b1) {
    asm volatile("mma.sync.aligned.m16n8k32.row.col.s32.s8.s8.s32 "
                 "{%0,%1,%2,%3},{%4,%5,%6,%7},{%8,%9},{%0,%1,%2,%3};"
                 : "+r"(d[0]), "+r"(d[1]), "+r"(d[2]), "+r"(d[3])
                 : "r"(a0), "r"(a1), "r"(a2), "r"(a3), "r"(b0), "r"(b1));
}
__device__ __forceinline__ void ldsm4(unsigned& r0, unsigned& r1, unsigned& r2, unsigned& r3, unsigned addr) {
    asm volatile("ldmatrix.sync.aligned.m8n8.x4.shared.b16 {%0,%1,%2,%3},[%4];"
                 : "=r"(r0), "=r"(r1), "=r"(r2), "=r"(r3) : "r"(addr));
}
__device__ __forceinline__ void ldsm2(unsigned& r0, unsigned& r1, unsigned addr) {
    asm volatile("ldmatrix.sync.aligned.m8n8.x2.shared.b16 {%0,%1},[%2];"
                 : "=r"(r0), "=r"(r1) : "r"(addr));
}

__global__ void __launch_bounds__(256) conv2_mma3_kernel(const float* __restrict__ b2) {
    extern __shared__ __align__(16) unsigned char smem[];
    unsigned sbase = (unsigned)__cvta_generic_to_shared(smem);
    int tid = threadIdx.x, wid = tid >> 5, lane = tid & 31;
    int gr = lane >> 2, tig = lane & 3;
    int j8 = lane >> 3, r8 = lane & 7;

    // stage B (2520 uint4), thresholds, both images (810 uint4)
    {
        const uint4* s = (const uint4*)g_w2i8;
        uint4* d = (uint4*)(smem + OFF_B);
        for (int t = tid; t < 2520; t += 256) d[t] = s[t];
    }
    if (tid < 50) ((int*)(smem + OFF_THR))[tid] = (int)floorf(-b2[tid]) + 1;
    {
        const uint4* s = (const uint4*)(g_a1 + (size_t)blockIdx.x * 12960);
        uint4* d = (uint4*)(smem + OFF_IMG);
        for (int t = tid; t < 810; t += 256) d[t] = s[t];
    }
    __syncthreads();

    bool has1 = (wid < 5);
    unsigned aRowOff = (unsigned)(r8 + ((j8 & 1) << 3));
    unsigned aByte = (unsigned)((j8 >> 1) << 4);
    unsigned jb = (unsigned)((lane >> 3) & 1), rbl = (unsigned)(lane & 7);

    #pragma unroll 1
    for (int img = 0; img < 2; img++) {
        if (tid < 80) ((unsigned*)(smem + OFF_PACK))[tid] = 0u;

        int acc[2][NT][4];
        #pragma unroll
        for (int m = 0; m < 2; m++)
            #pragma unroll
            for (int n = 0; n < NT; n++)
                #pragma unroll
                for (int k = 0; k < 4; k++) acc[m][n][k] = 0;

        #pragma unroll 1
        for (int ky = 0; ky < 5; ky++) {
            if (tid < 196) {
                int cy = tid / 14, cx = tid % 14;
                const unsigned* src = (const unsigned*)(smem + OFF_IMG + img*6480 + ((cy + ky)*18 + cx)*20);
                unsigned v[32];
                #pragma unroll
                for (int q = 0; q < 25; q++) v[q] = src[q];
                #pragma unroll
                for (int q = 25; q < 32; q++) v[q] = 0u;
                uint4* dst = (uint4*)(smem + OFF_AV + tid*144);
                #pragma unroll
                for (int q = 0; q < 8; q++) dst[q] = make_uint4(v[q*4], v[q*4+1], v[q*4+2], v[q*4+3]);
            }
            __syncthreads();

            #pragma unroll
            for (int ks = 0; ks < 4; ks++) {
                unsigned a00,a01,a02,a03, a10=0,a11=0,a12=0,a13=0;
                ldsm4(a00,a01,a02,a03, sbase + OFF_AV + (wid*16 + aRowOff)*144 + ks*32 + aByte);
                if (has1)
                    ldsm4(a10,a11,a12,a13, sbase + OFF_AV + ((8 + wid)*16 + aRowOff)*144 + ks*32 + aByte);
                #pragma unroll
                for (int nt = 0; nt < NT; nt++) {
                    unsigned b0, b1;
                    ldsm2(b0, b1, sbase + OFF_B + ky*8064 + (nt*8 + rbl)*144 + ks*32 + jb*16);
                    mma_s8(acc[0][nt], a00,a01,a02,a03, b0,b1);
                    if (has1) mma_s8(acc[1][nt], a10,a11,a12,a13, b0,b1);
                }
            }
            __syncthreads();
        }

        // dump conv values to V (int16 [208][56], row stride 112B) — aliases A (A dead now)
        {
            unsigned* V = (unsigned*)(smem + OFF_AV);
            #pragma unroll
            for (int mt = 0; mt < 2; mt++) {
                if (mt == 1 && !has1) break;
                int mb = (mt == 0 ? wid : 8 + wid) * 16;
                #pragma unroll
                for (int nt = 0; nt < NT; nt++) {
                    int n = nt*8 + 2*tig;
                    int m = mb + gr;
                    V[m*28 + (n >> 1)]     = ((unsigned)acc[mt][nt][0] & 0xffffu) | ((unsigned)acc[mt][nt][1] << 16);
                    V[(m+8)*28 + (n >> 1)] = ((unsigned)acc[mt][nt][2] & 0xffffu) | ((unsigned)acc[mt][nt][3] << 16);
                }
            }
        }
        __syncthreads();

        // pool + threshold + pack bits (bit index pp*50 + f)
        {
            const short* V = (const short*)(smem + OFF_AV);
            const int* thr = (const int*)(smem + OFF_THR);
            unsigned* pack = (unsigned*)(smem + OFF_PACK);
            for (int it = tid; it < 2450; it += 256) {
                int pp = it / 50, f = it % 50;
                int y = pp / 7, x = pp % 7;
                int m00 = (2*y)*14 + 2*x;
                int v0 = V[m00*56 + f];
                int v1 = V[(m00+1)*56 + f];
                int v2 = V[(m00+14)*56 + f];
                int v3 = V[(m00+15)*56 + f];
                int mx = max(max(v0, v1), max(v2, v3));
                if (mx >= thr[f]) {
                    int bi = pp*50 + f;
                    atomicOr(&pack[bi >> 5], 1u << (bi & 31));
                }
            }
        }
        __syncthreads();
        if (tid < 20)
            ((uint4*)(g_packed2 + (size_t)(2*blockIdx.x + img)*80))[tid] = ((const uint4*)(smem + OFF_PACK))[tid];
        __syncthreads();
    }
}

// ---------------- fc3: register-tiled 4 outputs x 8 batches per thread ----------------
__global__ void __launch_bounds__(128) fc3_kernel(const float* __restrict__ b3) {
    __shared__ __align__(16) unsigned sa[8*80];
    __shared__ int sna[8];
    int tid = threadIdx.x;
    int b0 = blockIdx.y * 8;
    for (int t = tid; t < 160; t += 128)
        ((uint4*)sa)[t] = ((const uint4*)(g_packed2 + b0*80))[t];
    __syncthreads();
    if (tid < 8) {
        int s = 0;
        #pragma unroll 8
        for (int i = 0; i < 80; i++) s += __popc(sa[tid*80 + i]);
        sna[tid] = s;
    }
    __syncthreads();

    int obase = blockIdx.x * 512 + tid;
    const uint4* wr0 = (const uint4*)(g_w3p + (obase      )*80);
    const uint4* wr1 = (const uint4*)(g_w3p + (obase + 128)*80);
    const uint4* wr2 = (const uint4*)(g_w3p + (obase + 256)*80);
    const uint4* wr3 = (const uint4*)(g_w3p + (obase + 384)*80);

    int cnt[4][8];
    #pragma unroll
    for (int j = 0; j < 4; j++)
        #pragma unroll
        for (int bb = 0; bb < 8; bb++) cnt[j][bb] = 0;

    #pragma unroll 2
    for (int i = 0; i < 20; i++) {
        uint4 w[4] = {wr0[i], wr1[i], wr2[i], wr3[i]};
        #pragma unroll
        for (int bb = 0; bb < 8; bb++) {
            uint4 a = *(const uint4*)&sa[bb*80 + i*4];
            #pragma unroll
            for (int j = 0; j < 4; j++) {
                cnt[j][bb] += __popc(a.x & w[j].x) + __popc(a.y & w[j].y)
                            + __popc(a.z & w[j].z) + __popc(a.w & w[j].w);
            }
        }
    }

    #pragma unroll
    for (int j = 0; j < 4; j++) {
        int o = obase + 128*j;
        float bias = b3[o];
        int widx = o >> 5;
        #pragma unroll
        for (int bb = 0; bb < 8; bb++) {
            float val = (float)(2*cnt[j][bb] - sna[bb]) + bias;
            unsigned word = __ballot_sync(0xffffffffu, val > 0.0f);
            if ((tid & 31) == 0) g_packed3[(b0 + bb)*32 + widx] = word;
        }
    }
}

// ---------------- fc4 ----------------
__global__ void __launch_bounds__(128) fc4_kernel(const float* __restrict__ b4, float* __restrict__ out) {
    __shared__ unsigned w4s[10*32];
    __shared__ float b4s[10];
    int tid = threadIdx.x;
    for (int t = tid; t < 320; t += 128) w4s[t] = g_w4p[t];
    if (tid < 10) b4s[tid] = b4[tid];
    __syncthreads();

    int b = blockIdx.x * 128 + tid;
    unsigned a[32]; int na = 0;
    #pragma unroll
    for (int i = 0; i < 32; i++) { a[i] = g_packed3[b*32 + i]; na += __popc(a[i]); }
    #pragma unroll
    for (int k = 0; k < 10; k++) {
        int cnt = 0;
        #pragma unroll
        for (int i = 0; i < 32; i++) cnt += __popc(a[i] & w4s[k*32 + i]);
        out[b*10 + k] = (float)(2*cnt - na) + b4s[k];
    }
}

// ---------------- launch ----------------
extern "C" void kernel_launch(void* const* d_in, const int* in_sizes, int n_in,
                              void* d_out, int out_size) {
    const float* x  = (const float*)d_in[0];
    const float* w1 = (const float*)d_in[1];
    const float* b1 = (const float*)d_in[2];
    const float* w2 = (const float*)d_in[3];
    const float* b2 = (const float*)d_in[4];
    const float* w3 = (const float*)d_in[5];
    const float* b3 = (const float*)d_in[6];
    const float* w4 = (const float*)d_in[7];
    const float* b4 = (const float*)d_in[8];
    float* out = (float*)d_out;

    cudaFuncSetAttribute(conv2_mma3_kernel, cudaFuncAttributeMaxDynamicSharedMemorySize, SMEM_SZ);

    pack_w3_kernel<<<1024, 128>>>(w3);               // block per out-neuron
    pack_wsm_kernel<<<318, 128>>>(w1, w2, w4);       // 40660 items
    pack_xrow_kernel<<<1024, 128>>>(x);              // 4096*32 rows
    conv1_kernel<<<6272, 128>>>(b1);                 // 4096*196
    conv2_mma3_kernel<<<2048, 256, SMEM_SZ>>>(b2);   // 2 images per CTA, 2 CTAs/SM
    fc3_kernel<<<dim3(2, 512), 128>>>(b3);           // 1024 outs x (4096/8)
    fc4_kernel<<<32, 128>>>(b4, out);                // 4096
}

// round 14
// speedup vs baseline: 1.0784x; 1.0710x over previous
#include <cuda_runtime.h>

#define BATCH 4096

// ---------------- Device scratch ----------------
__device__ unsigned g_w1p[20];                         // 25 sign bits per filter
__device__ __align__(16) unsigned g_w2q[50*16];        // per filter: 500-bit window layout (p = t*20+c)
__device__ __align__(16) unsigned g_w3p[1024*80];      // per out-neuron: 2450 bits, order j' = pix*50+c, pad 80
__device__ unsigned g_w4p[10*32];                      // per out-neuron: 1024 sign bits
__device__ unsigned g_xrow[BATCH*64];                  // per image: [0..31]=mask rows, [32..63]=sign rows (bit xx+2)
__device__ unsigned g_packed1[BATCH*196];              // conv2 input: 20 ch bits per 14x14 pixel
__device__ __align__(16) unsigned g_packed2[BATCH*80]; // fc3 input bits (order pix*50+c), padded
__device__ unsigned g_packed3[BATCH*32];               // fc4 input bits (1024)

// ---------------- fused packing: w3 (coalesced) | xrow | small weights ----------------
// blocks [0,1024): w3 neuron per block | [1024,2048): xrow | [2048,2057): w1/w2q/w4
__global__ void __launch_bounds__(128) pack_all_kernel(const float* __restrict__ x,
                                                       const float* __restrict__ w1,
                                                       const float* __restrict__ w2,
                                                       const float* __restrict__ w3,
                                                       const float* __restrict__ w4) {
    int bid = blockIdx.x, tid = threadIdx.x;
    if (bid < 1024) {
        // w3: coalesced read, smem transpose to permuted bit order
        __shared__ unsigned char sb[2450];
        const float* row = w3 + bid * 2450;
        for (int j = tid; j < 2450; j += 128) sb[j] = (row[j] > 0.0f);
        __syncthreads();
        if (tid < 80) {
            unsigned m = 0; int base = tid * 32;
            for (int k = 0; k < 32; k++) {
                int jp = base + k;
                if (jp < 2450) {
                    int pix = jp / 50, c = jp % 50;   // orig flat index = c*49 + pix
                    m |= (unsigned)sb[c*49 + pix] << k;
                }
            }
            g_w3p[bid*80 + tid] = m;
        }
    } else if (bid < 2048) {
        // xrow: per-row mask/sign bit words
        int id = (bid - 1024) * 128 + tid;            // 4096*32
        int b = id >> 5, r = id & 31;
        unsigned m = 0, p = 0;
        if (r >= 2 && r < 30) {
            const float* row = x + b*784 + (r-2)*28;
            #pragma unroll
            for (int xx = 0; xx < 28; xx++) {
                float v = row[xx];
                m |= (unsigned)(v != 0.0f) << (xx + 2);
                p |= (unsigned)(v > 0.0f)  << (xx + 2);
            }
        }
        g_xrow[b*64 + r]      = m;
        g_xrow[b*64 + 32 + r] = p;
    } else {
        int id = (bid - 2048) * 128 + tid;            // 1140 items
        if (id < 20) {
            unsigned m = 0;
            #pragma unroll
            for (int t = 0; t < 25; t++) m |= (unsigned)(w1[id*25 + t] > 0.0f) << t;
            g_w1p[id] = m;
        } else if (id < 820) {
            int idx = id - 20; int f = idx / 16, w = idx % 16;
            unsigned m = 0;
            for (int k = 0; k < 32; k++) {
                int p = w*32 + k;
                if (p < 500) {
                    int t = p / 20, c = p % 20;
                    m |= (unsigned)(w2[f*500 + c*25 + t] > 0.0f) << k;
                }
            }
            g_w2q[idx] = m;
        } else if (id < 1140) {
            int idx = id - 820; int o = idx / 32, w = idx % 32;
            unsigned m = 0;
            #pragma unroll
            for (int k = 0; k < 32; k++) m |= (unsigned)(w4[o*1024 + w*32 + k] > 0.0f) << k;
            g_w4p[idx] = m;
        }
    }
}

// ---------------- conv1 + relu + maxpool2 + sign -> packed channel bits (R4-measured) ----------------
__global__ void __launch_bounds__(128) conv1_kernel(const float* __restrict__ b1) {
    __shared__ unsigned w1s[20];
    __shared__ float b1s[20];
    int tid = threadIdx.x;
    if (tid < 20) { w1s[tid] = g_w1p[tid]; b1s[tid] = b1[tid]; }
    __syncthreads();

    int id = blockIdx.x * 128 + tid;                 // 6272*128 = 4096*196
    if (id < BATCH*80) g_packed2[id] = 0;            // zero fc3-input rows for conv2's atomicOr
    int b = id / 196, pix = id % 196;
    int py = pix / 14, px = pix % 14;
    const unsigned* xr = g_xrow + b*64;

    unsigned mr[6], pr[6];
    #pragma unroll
    for (int i = 0; i < 6; i++) { mr[i] = xr[2*py + i]; pr[i] = xr[32 + 2*py + i]; }

    unsigned M[4], P[4]; int pm[4];
    #pragma unroll
    for (int dy = 0; dy < 2; dy++)
    #pragma unroll
    for (int dx = 0; dx < 2; dx++) {
        int sh = 2*px + dx;
        unsigned m = 0, p = 0;
        #pragma unroll
        for (int ky = 0; ky < 5; ky++) {
            m |= ((mr[dy + ky] >> sh) & 31u) << (5*ky);
            p |= ((pr[dy + ky] >> sh) & 31u) << (5*ky);
        }
        int w = dy*2 + dx;
        M[w] = m; P[w] = p; pm[w] = __popc(m);
    }

    unsigned word = 0;
    #pragma unroll
    for (int c = 0; c < 20; c++) {
        unsigned wp = w1s[c];
        int d0 = 2*__popc(M[0] & ~(P[0] ^ wp)) - pm[0];
        int d1 = 2*__popc(M[1] & ~(P[1] ^ wp)) - pm[1];
        int d2 = 2*__popc(M[2] & ~(P[2] ^ wp)) - pm[2];
        int d3 = 2*__popc(M[3] & ~(P[3] ^ wp)) - pm[3];
        int mx = max(max(d0, d1), max(d2, d3));
        if ((float)mx + b1s[c] > 0.0f) word |= 1u << c;
    }
    g_packed1[id] = word;
}

// ---------------- conv2: dense 512-bit window packing (R4-measured, 162.3us) ----------------
template<int BASE>
__device__ __forceinline__ void pack_window(const unsigned iw[36], unsigned W[16]) {
    unsigned long long acc = 0; int off = 0; int wi = 0;
    #pragma unroll
    for (int ky = 0; ky < 5; ky++) {
        #pragma unroll
        for (int kx = 0; kx < 5; kx++) {
            unsigned long long v = iw[BASE + ky*6 + kx];
            acc |= v << off;
            off += 20;
            if (off >= 32) { W[wi++] = (unsigned)acc; acc >>= 32; off -= 32; }
        }
    }
    W[wi] = (unsigned)acc;
}

__global__ void __launch_bounds__(128) conv2_kernel(const float* __restrict__ b2) {
    __shared__ __align__(16) unsigned sw[50*16];
    __shared__ float b2s[50];
    int tid = threadIdx.x;
    for (int t = tid; t < 800; t += 128) sw[t] = g_w2q[t];
    if (tid < 50) b2s[tid] = b2[tid];
    __syncthreads();

    int id = blockIdx.x * 128 + tid;                 // 1568*128 = 4096*49
    int b = id / 49, pix = id % 49;
    int py = pix / 7, px = pix % 7;
    const unsigned* inb = g_packed1 + b * 196;

    unsigned iw[36];
    #pragma unroll
    for (int i = 0; i < 6; i++) {
        int y = py*2 - 2 + i;
        #pragma unroll
        for (int j = 0; j < 6; j++) {
            int xx = px*2 - 2 + j;
            unsigned v = 0u;
            if ((unsigned)y < 14u && (unsigned)xx < 14u) v = inb[y*14 + xx];
            iw[i*6+j] = v;
        }
    }

    unsigned W0[16], W1[16], W2[16], W3[16];
    pack_window<0>(iw, W0);
    pack_window<1>(iw, W1);
    pack_window<6>(iw, W2);
    pack_window<7>(iw, W3);

    int S0=0,S1=0,S2=0,S3=0;
    #pragma unroll
    for (int j = 0; j < 16; j++) {
        S0 += __popc(W0[j]); S1 += __popc(W1[j]);
        S2 += __popc(W2[j]); S3 += __popc(W3[j]);
    }

    unsigned long long bits = 0ull;
    for (int f = 0; f < 50; f++) {
        const uint4* fp = (const uint4*)&sw[f*16];
        int P0=0,P1=0,P2=0,P3=0;
        #pragma unroll
        for (int q = 0; q < 4; q++) {
            uint4 w = fp[q];
            unsigned fw[4] = {w.x, w.y, w.z, w.w};
            #pragma unroll
            for (int k = 0; k < 4; k++) {
                int j = q*4 + k;
                P0 += __popc(W0[j] & fw[k]);
                P1 += __popc(W1[j] & fw[k]);
                P2 += __popc(W2[j] & fw[k]);
                P3 += __popc(W3[j] & fw[k]);
            }
        }
        int mx = max(max(2*P0 - S0, 2*P1 - S1), max(2*P2 - S2, 2*P3 - S3));
        bits |= (unsigned long long)((float)mx + b2s[f] > 0.0f) << f;
    }

    unsigned* row = g_packed2 + b * 80;
    int base = pix * 50;
    int w0 = base >> 5, sh = base & 31;
    unsigned long long lo = bits << sh;
    atomicOr(&row[w0],     (unsigned)lo);
    atomicOr(&row[w0 + 1], (unsigned)(lo >> 32));
    if (sh >= 15) atomicOr(&row[w0 + 2], (unsigned)(bits >> (64 - sh)));
}

// ---------------- fc3: register-tiled 4 outputs x 8 batches per thread (R4-measured) ----------------
__global__ void __launch_bounds__(128) fc3_kernel(const float* __restrict__ b3) {
    __shared__ __align__(16) unsigned sa[8*80];
    __shared__ int sna[8];
    int tid = threadIdx.x;
    int b0 = blockIdx.y * 8;
    for (int t = tid; t < 160; t += 128)
        ((uint4*)sa)[t] = ((const uint4*)(g_packed2 + b0*80))[t];
    __syncthreads();
    if (tid < 8) {
        int s = 0;
        #pragma unroll 8
        for (int i = 0; i < 80; i++) s += __popc(sa[tid*80 + i]);
        sna[tid] = s;
    }
    __syncthreads();

    int obase = blockIdx.x * 512 + tid;              // outputs obase + 128*j, j=0..3
    const uint4* wr0 = (const uint4*)(g_w3p + (obase      )*80);
    const uint4* wr1 = (const uint4*)(g_w3p + (obase + 128)*80);
    const uint4* wr2 = (const uint4*)(g_w3p + (obase + 256)*80);
    const uint4* wr3 = (const uint4*)(g_w3p + (obase + 384)*80);

    int cnt[4][8];
    #pragma unroll
    for (int j = 0; j < 4; j++)
        #pragma unroll
        for (int bb = 0; bb < 8; bb++) cnt[j][bb] = 0;

    #pragma unroll 2
    for (int i = 0; i < 20; i++) {
        uint4 w[4] = {wr0[i], wr1[i], wr2[i], wr3[i]};
        #pragma unroll
        for (int bb = 0; bb < 8; bb++) {
            uint4 a = *(const uint4*)&sa[bb*80 + i*4];
            #pragma unroll
            for (int j = 0; j < 4; j++) {
                cnt[j][bb] += __popc(a.x & w[j].x) + __popc(a.y & w[j].y)
                            + __popc(a.z & w[j].z) + __popc(a.w & w[j].w);
            }
        }
    }

    #pragma unroll
    for (int j = 0; j < 4; j++) {
        int o = obase + 128*j;
        float bias = b3[o];
        int widx = o >> 5;
        #pragma unroll
        for (int bb = 0; bb < 8; bb++) {
            float val = (float)(2*cnt[j][bb] - sna[bb]) + bias;
            unsigned word = __ballot_sync(0xffffffffu, val > 0.0f);
            if ((tid & 31) == 0) g_packed3[(b0 + bb)*32 + widx] = word;
        }
    }
}

// ---------------- fc4 (R4-measured) ----------------
__global__ void __launch_bounds__(128) fc4_kernel(const float* __restrict__ b4, float* __restrict__ out) {
    __shared__ unsigned w4s[10*32];
    __shared__ float b4s[10];
    int tid = threadIdx.x;
    for (int t = tid; t < 320; t += 128) w4s[t] = g_w4p[t];
    if (tid < 10) b4s[tid] = b4[tid];
    __syncthreads();

    int b = blockIdx.x * 128 + tid;                  // 32*128 = 4096
    unsigned a[32]; int na = 0;
    #pragma unroll
    for (int i = 0; i < 32; i++) { a[i] = g_packed3[b*32 + i]; na += __popc(a[i]); }
    #pragma unroll
    for (int k = 0; k < 10; k++) {
        int cnt = 0;
        #pragma unroll
        for (int i = 0; i < 32; i++) cnt += __popc(a[i] & w4s[k*32 + i]);
        out[b*10 + k] = (float)(2*cnt - na) + b4s[k];
    }
}

// ---------------- launch ----------------
extern "C" void kernel_launch(void* const* d_in, const int* in_sizes, int n_in,
                              void* d_out, int out_size) {
    const float* x  = (const float*)d_in[0];
    const float* w1 = (const float*)d_in[1];
    const float* b1 = (const float*)d_in[2];
    const float* w2 = (const float*)d_in[3];
    const float* b2 = (const float*)d_in[4];
    const float* w3 = (const float*)d_in[5];
    const float* b3 = (const float*)d_in[6];
    const float* w4 = (const float*)d_in[7];
    const float* b4 = (const float*)d_in[8];
    float* out = (float*)d_out;

    pack_all_kernel<<<2057, 128>>>(x, w1, w2, w3, w4);  // w3 | xrow | small weights
    conv1_kernel<<<6272, 128>>>(b1);                    // 4096*196 (+ zeroes g_packed2)
    conv2_kernel<<<1568, 128>>>(b2);                    // 4096*49
    fc3_kernel<<<dim3(2, 512), 128>>>(b3);              // 1024 outs x (4096/8)
    fc4_kernel<<<32, 128>>>(b4, out);                   // 4096
}

// round 15
// speedup vs baseline: 1.0876x; 1.0086x over previous
#include <cuda_runtime.h>

#define BATCH 4096

// ---------------- Device scratch ----------------
__device__ unsigned g_w1p[20];                         // 25 sign bits per filter
__device__ __align__(16) unsigned g_w2q[50*16];        // per filter: 500-bit window layout (p = t*20+c)
__device__ __align__(16) unsigned g_w3p[1024*80];      // per out-neuron: 2450 bits, order j' = pix*50+c, pad 80
__device__ unsigned g_w4p[10*32];                      // per out-neuron: 1024 sign bits
__device__ unsigned g_xrow[BATCH*64];                  // per image: [0..31]=mask rows, [32..63]=sign rows (bit xx+2)
__device__ unsigned g_packed1[BATCH*196];              // conv2 input: 20 ch bits per 14x14 pixel
__device__ __align__(16) unsigned g_packed2[BATCH*80]; // fc3 input bits (order pix*50+c), padded
__device__ unsigned g_packed3[BATCH*32];               // fc4 input bits (1024)

// ---------------- fused packing: w3 (coalesced) | xrow | small weights ----------------
// blocks [0,1024): w3 neuron per block | [1024,2048): xrow | [2048,2057): w1/w2q/w4
__global__ void __launch_bounds__(128) pack_all_kernel(const float* __restrict__ x,
                                                       const float* __restrict__ w1,
                                                       const float* __restrict__ w2,
                                                       const float* __restrict__ w3,
                                                       const float* __restrict__ w4) {
    int bid = blockIdx.x, tid = threadIdx.x;
    if (bid < 1024) {
        __shared__ unsigned char sb[2450];
        const float* row = w3 + bid * 2450;
        for (int j = tid; j < 2450; j += 128) sb[j] = (row[j] > 0.0f);
        __syncthreads();
        if (tid < 80) {
            unsigned m = 0; int base = tid * 32;
            for (int k = 0; k < 32; k++) {
                int jp = base + k;
                if (jp < 2450) {
                    int pix = jp / 50, c = jp % 50;   // orig flat index = c*49 + pix
                    m |= (unsigned)sb[c*49 + pix] << k;
                }
            }
            g_w3p[bid*80 + tid] = m;
        }
    } else if (bid < 2048) {
        int id = (bid - 1024) * 128 + tid;            // 4096*32
        int b = id >> 5, r = id & 31;
        unsigned m = 0, p = 0;
        if (r >= 2 && r < 30) {
            const float* row = x + b*784 + (r-2)*28;
            #pragma unroll
            for (int xx = 0; xx < 28; xx++) {
                float v = row[xx];
                m |= (unsigned)(v != 0.0f) << (xx + 2);
                p |= (unsigned)(v > 0.0f)  << (xx + 2);
            }
        }
        g_xrow[b*64 + r]      = m;
        g_xrow[b*64 + 32 + r] = p;
    } else {
        int id = (bid - 2048) * 128 + tid;            // 1140 items
        if (id < 20) {
            unsigned m = 0;
            #pragma unroll
            for (int t = 0; t < 25; t++) m |= (unsigned)(w1[id*25 + t] > 0.0f) << t;
            g_w1p[id] = m;
        } else if (id < 820) {
            int idx = id - 20; int f = idx / 16, w = idx % 16;
            unsigned m = 0;
            for (int k = 0; k < 32; k++) {
                int p = w*32 + k;
                if (p < 500) {
                    int t = p / 20, c = p % 20;
                    m |= (unsigned)(w2[f*500 + c*25 + t] > 0.0f) << k;
                }
            }
            g_w2q[idx] = m;
        } else if (id < 1140) {
            int idx = id - 820; int o = idx / 32, w = idx % 32;
            unsigned m = 0;
            #pragma unroll
            for (int k = 0; k < 32; k++) m |= (unsigned)(w4[o*1024 + w*32 + k] > 0.0f) << k;
            g_w4p[idx] = m;
        }
    }
}

// ---------------- conv1 + relu + maxpool2 + sign -> packed channel bits ----------------
__global__ void __launch_bounds__(128) conv1_kernel(const float* __restrict__ b1) {
    __shared__ unsigned w1s[20];
    __shared__ float b1s[20];
    int tid = threadIdx.x;
    if (tid < 20) { w1s[tid] = g_w1p[tid]; b1s[tid] = b1[tid]; }
    __syncthreads();

    int id = blockIdx.x * 128 + tid;                 // 6272*128 = 4096*196
    if (id < BATCH*80) g_packed2[id] = 0;            // zero fc3-input rows for conv2's atomicOr
    int b = id / 196, pix = id % 196;
    int py = pix / 14, px = pix % 14;
    const unsigned* xr = g_xrow + b*64;

    unsigned mr[6], pr[6];
    #pragma unroll
    for (int i = 0; i < 6; i++) { mr[i] = xr[2*py + i]; pr[i] = xr[32 + 2*py + i]; }

    unsigned M[4], P[4]; int pm[4];
    #pragma unroll
    for (int dy = 0; dy < 2; dy++)
    #pragma unroll
    for (int dx = 0; dx < 2; dx++) {
        int sh = 2*px + dx;
        unsigned m = 0, p = 0;
        #pragma unroll
        for (int ky = 0; ky < 5; ky++) {
            m |= ((mr[dy + ky] >> sh) & 31u) << (5*ky);
            p |= ((pr[dy + ky] >> sh) & 31u) << (5*ky);
        }
        int w = dy*2 + dx;
        M[w] = m; P[w] = p; pm[w] = __popc(m);
    }

    unsigned word = 0;
    #pragma unroll
    for (int c = 0; c < 20; c++) {
        unsigned wp = w1s[c];
        int d0 = 2*__popc(M[0] & ~(P[0] ^ wp)) - pm[0];
        int d1 = 2*__popc(M[1] & ~(P[1] ^ wp)) - pm[1];
        int d2 = 2*__popc(M[2] & ~(P[2] ^ wp)) - pm[2];
        int d3 = 2*__popc(M[3] & ~(P[3] ^ wp)) - pm[3];
        int mx = max(max(d0, d1), max(d2, d3));
        if ((float)mx + b1s[c] > 0.0f) word |= 1u << c;
    }
    g_packed1[id] = word;
}

// ---------------- conv2: dense 512-bit window packing (best measured: 162.3us) ----------------
template<int BASE>
__device__ __forceinline__ void pack_window(const unsigned iw[36], unsigned W[16]) {
    unsigned long long acc = 0; int off = 0; int wi = 0;
    #pragma unroll
    for (int ky = 0; ky < 5; ky++) {
        #pragma unroll
        for (int kx = 0; kx < 5; kx++) {
            unsigned long long v = iw[BASE + ky*6 + kx];
            acc |= v << off;
            off += 20;
            if (off >= 32) { W[wi++] = (unsigned)acc; acc >>= 32; off -= 32; }
        }
    }
    W[wi] = (unsigned)acc;
}

__global__ void __launch_bounds__(128) conv2_kernel(const float* __restrict__ b2) {
    __shared__ __align__(16) unsigned sw[50*16];
    __shared__ float b2s[50];
    int tid = threadIdx.x;
    for (int t = tid; t < 800; t += 128) sw[t] = g_w2q[t];
    if (tid < 50) b2s[tid] = b2[tid];
    __syncthreads();

    int id = blockIdx.x * 128 + tid;                 // 1568*128 = 4096*49
    int b = id / 49, pix = id % 49;
    int py = pix / 7, px = pix % 7;
    const unsigned* inb = g_packed1 + b * 196;

    unsigned iw[36];
    #pragma unroll
    for (int i = 0; i < 6; i++) {
        int y = py*2 - 2 + i;
        #pragma unroll
        for (int j = 0; j < 6; j++) {
            int xx = px*2 - 2 + j;
            unsigned v = 0u;
            if ((unsigned)y < 14u && (unsigned)xx < 14u) v = inb[y*14 + xx];
            iw[i*6+j] = v;
        }
    }

    unsigned W0[16], W1[16], W2[16], W3[16];
    pack_window<0>(iw, W0);
    pack_window<1>(iw, W1);
    pack_window<6>(iw, W2);
    pack_window<7>(iw, W3);

    int S0=0,S1=0,S2=0,S3=0;
    #pragma unroll
    for (int j = 0; j < 16; j++) {
        S0 += __popc(W0[j]); S1 += __popc(W1[j]);
        S2 += __popc(W2[j]); S3 += __popc(W3[j]);
    }

    unsigned long long bits = 0ull;
    for (int f = 0; f < 50; f++) {
        const uint4* fp = (const uint4*)&sw[f*16];
        int P0=0,P1=0,P2=0,P3=0;
        #pragma unroll
        for (int q = 0; q < 4; q++) {
            uint4 w = fp[q];
            unsigned fw[4] = {w.x, w.y, w.z, w.w};
            #pragma unroll
            for (int k = 0; k < 4; k++) {
                int j = q*4 + k;
                P0 += __popc(W0[j] & fw[k]);
                P1 += __popc(W1[j] & fw[k]);
                P2 += __popc(W2[j] & fw[k]);
                P3 += __popc(W3[j] & fw[k]);
            }
        }
        int mx = max(max(2*P0 - S0, 2*P1 - S1), max(2*P2 - S2, 2*P3 - S3));
        bits |= (unsigned long long)((float)mx + b2s[f] > 0.0f) << f;
    }

    unsigned* row = g_packed2 + b * 80;
    int base = pix * 50;
    int w0 = base >> 5, sh = base & 31;
    unsigned long long lo = bits << sh;
    atomicOr(&row[w0],     (unsigned)lo);
    atomicOr(&row[w0 + 1], (unsigned)(lo >> 32));
    if (sh >= 15) atomicOr(&row[w0 + 2], (unsigned)(bits >> (64 - sh)));
}

// ---------------- fc3: 2 outputs x 8 batches per thread (occupancy fix) ----------------
__global__ void __launch_bounds__(128) fc3_kernel(const float* __restrict__ b3) {
    __shared__ __align__(16) unsigned sa[8*80];
    __shared__ int sna[8];
    int tid = threadIdx.x;
    int b0 = blockIdx.y * 8;
    for (int t = tid; t < 160; t += 128)
        ((uint4*)sa)[t] = ((const uint4*)(g_packed2 + b0*80))[t];
    __syncthreads();
    if (tid < 8) {
        int s = 0;
        #pragma unroll 8
        for (int i = 0; i < 80; i++) s += __popc(sa[tid*80 + i]);
        sna[tid] = s;
    }
    __syncthreads();

    int obase = blockIdx.x * 256 + tid;              // outputs obase, obase+128
    const uint4* wr0 = (const uint4*)(g_w3p + (obase      )*80);
    const uint4* wr1 = (const uint4*)(g_w3p + (obase + 128)*80);

    int cnt[2][8];
    #pragma unroll
    for (int j = 0; j < 2; j++)
        #pragma unroll
        for (int bb = 0; bb < 8; bb++) cnt[j][bb] = 0;

    #pragma unroll 2
    for (int i = 0; i < 20; i++) {
        uint4 w0 = wr0[i], w1 = wr1[i];
        #pragma unroll
        for (int bb = 0; bb < 8; bb++) {
            uint4 a = *(const uint4*)&sa[bb*80 + i*4];
            cnt[0][bb] += __popc(a.x & w0.x) + __popc(a.y & w0.y)
                        + __popc(a.z & w0.z) + __popc(a.w & w0.w);
            cnt[1][bb] += __popc(a.x & w1.x) + __popc(a.y & w1.y)
                        + __popc(a.z & w1.z) + __popc(a.w & w1.w);
        }
    }

    #pragma unroll
    for (int j = 0; j < 2; j++) {
        int o = obase + 128*j;
        float bias = b3[o];
        int widx = o >> 5;
        #pragma unroll
        for (int bb = 0; bb < 8; bb++) {
            float val = (float)(2*cnt[j][bb] - sna[bb]) + bias;
            unsigned word = __ballot_sync(0xffffffffu, val > 0.0f);
            if ((tid & 31) == 0) g_packed3[(b0 + bb)*32 + widx] = word;
        }
    }
}

// ---------------- fc4 ----------------
__global__ void __launch_bounds__(128) fc4_kernel(const float* __restrict__ b4, float* __restrict__ out) {
    __shared__ unsigned w4s[10*32];
    __shared__ float b4s[10];
    int tid = threadIdx.x;
    for (int t = tid; t < 320; t += 128) w4s[t] = g_w4p[t];
    if (tid < 10) b4s[tid] = b4[tid];
    __syncthreads();

    int b = blockIdx.x * 128 + tid;                  // 32*128 = 4096
    unsigned a[32]; int na = 0;
    #pragma unroll
    for (int i = 0; i < 32; i++) { a[i] = g_packed3[b*32 + i]; na += __popc(a[i]); }
    #pragma unroll
    for (int k = 0; k < 10; k++) {
        int cnt = 0;
        #pragma unroll
        for (int i = 0; i < 32; i++) cnt += __popc(a[i] & w4s[k*32 + i]);
        out[b*10 + k] = (float)(2*cnt - na) + b4s[k];
    }
}

// ---------------- launch ----------------
extern "C" void kernel_launch(void* const* d_in, const int* in_sizes, int n_in,
                              void* d_out, int out_size) {
    const float* x  = (const float*)d_in[0];
    const float* w1 = (const float*)d_in[1];
    const float* b1 = (const float*)d_in[2];
    const float* w2 = (const float*)d_in[3];
    const float* b2 = (const float*)d_in[4];
    const float* w3 = (const float*)d_in[5];
    const float* b3 = (const float*)d_in[6];
    const float* w4 = (const float*)d_in[7];
    const float* b4 = (const float*)d_in[8];
    float* out = (float*)d_out;

    pack_all_kernel<<<2057, 128>>>(x, w1, w2, w3, w4);  // w3 | xrow | small weights
    conv1_kernel<<<6272, 128>>>(b1);                    // 4096*196 (+ zeroes g_packed2)
    conv2_kernel<<<1568, 128>>>(b2);                    // 4096*49
    fc3_kernel<<<dim3(4, 512), 128>>>(b3);              // 1024 outs x (4096/8), 2x8 tile
    fc4_kernel<<<32, 128>>>(b4, out);                   // 4096
}